// round 12
// baseline (speedup 1.0000x reference)
#include <cuda_runtime.h>
#include <cuda_fp16.h>
#include <cstdint>

// Problem constants (fixed by the dataset)
#define NNODES 50000
#define LEV 2
#define RR 2
#define BLK (RR*LEV)          // 4 framelet blocks
#define NNZ 800000
#define F_IN 128
#define F_OUT 64
#define ACT_B (BLK - (LEV-1)) // 3 active blocks (block 0's y is never used)
#define ROWS_T (ACT_B * NNODES)   // 150000 (b, r) rows
#define EDGES_T (ACT_B * NNZ)     // 2400000 active edges
#define NB1 ((ROWS_T + 255) / 256)  // 586 level-1 scan blocks
#define GEMM_THREADS 800000         // 3125 blocks * 256
#define PADDED_E (EDGES_T + 3 * ROWS_T)   // 2,850,000 (pad-4 worst case)

// ---------------------------------------------------------------------------
// Scratch. h, y are fp16 (half2-packed): one row = 64 halves = 128 B = 8
// uint4. Edge list is PACKED AoS: edge = 4 B (uint16 col | fp16 val << 16);
// row segments padded to %4 so uint4 loads of 4 edges stay 16B-aligned.
//
// Cross-replay invariant: g_hist == 0 at entry. BSS zero-init covers the
// first run; spmm2_csr restores zero after its final read on every replay.
// ---------------------------------------------------------------------------
__device__ uint4  g_h[(size_t)NNODES * 8];     // 6.4 MB
__device__ uint4  g_y[(size_t)ROWS_T * 8];     // 19.2 MB
__device__ int    g_hist[ROWS_T];              // per-(b,r) nnz
__device__ int    g_start[ROWS_T];             // block-local padded excl prefix
__device__ int    g_cursor[ROWS_T];            // scatter cursors (block-local)
__device__ int    g_part[1024];                // scan block partials
__device__ uint4  g_ep4[(PADDED_E + 3) / 4];   // packed edges, 11.4 MB
#define g_ep ((unsigned*)g_ep4)

__device__ __forceinline__ unsigned pack_h2(float a, float b) {
    __half2 h = __floats2half2_rn(a, b);
    return *reinterpret_cast<unsigned*>(&h);
}
__device__ __forceinline__ float2 unpack_h2(unsigned u) {
    __half2 h = *reinterpret_cast<__half2*>(&u);
    return __half22float2(h);
}
__device__ __forceinline__ unsigned pack_edge(int c, float v) {
    return (unsigned)c | ((unsigned)__half_as_ushort(__float2half_rn(v)) << 16);
}
__device__ __forceinline__ float edge_val(unsigned e) {
    return __half2float(__ushort_as_half((unsigned short)(e >> 16)));
}
__device__ __forceinline__ void accum8(float* acc, float v, uint4 hv) {
    const float2 f0 = unpack_h2(hv.x);
    const float2 f1 = unpack_h2(hv.y);
    const float2 f2 = unpack_h2(hv.z);
    const float2 f3 = unpack_h2(hv.w);
    acc[0] += v * f0.x; acc[1] += v * f0.y;
    acc[2] += v * f1.x; acc[3] += v * f1.y;
    acc[4] += v * f2.x; acc[5] += v * f2.y;
    acc[6] += v * f3.x; acc[7] += v * f3.y;
}

// ---------------------------------------------------------------------------
// h = x @ W (fp32 compute, fp16 store) + fused edge histogram.
// ---------------------------------------------------------------------------
__global__ __launch_bounds__(256) void gemm_xw(const float* __restrict__ x,
                                               const float* __restrict__ w,
                                               const int*   __restrict__ rows) {
    const int t  = threadIdx.x;
    const int gt = blockIdx.x * 256 + t;

    __shared__ float4 ws[F_IN * (F_OUT/4)];   // 32 KB
    __shared__ float4 xs[16 * (F_IN/4)];      // 8 KB

    // 3 strided edges per thread (3 * 800000 == EDGES_T); REDs hide under GEMM.
    #pragma unroll
    for (int s = 0; s < 3; s++) {
        const int e = gt + s * GEMM_THREADS;
        const int b = e / NNZ;
        const int i = e - b * NNZ;
        const int r = rows[(size_t)(b + 1) * NNZ + i];
        atomicAdd(&g_hist[b * NNODES + r], 1);
    }

    #pragma unroll
    for (int i = 0; i < 8; i++)
        ws[t + i * 256] = ((const float4*)w)[t + i * 256];

    const size_t row0 = (size_t)blockIdx.x * 16;
    #pragma unroll
    for (int i = 0; i < 2; i++)
        xs[t + i * 256] = ((const float4*)x)[row0 * (F_IN/4) + t + i * 256];

    __syncthreads();

    const int fi = t & 15;
    const int ri = t >> 4;
    float4 acc = make_float4(0.f, 0.f, 0.f, 0.f);

    #pragma unroll
    for (int k = 0; k < F_IN; k += 4) {
        const float4 xv = xs[ri * (F_IN/4) + (k >> 2)];
        const float4 w0 = ws[(k + 0) * 16 + fi];
        const float4 w1 = ws[(k + 1) * 16 + fi];
        const float4 w2 = ws[(k + 2) * 16 + fi];
        const float4 w3 = ws[(k + 3) * 16 + fi];
        acc.x += xv.x * w0.x + xv.y * w1.x + xv.z * w2.x + xv.w * w3.x;
        acc.y += xv.x * w0.y + xv.y * w1.y + xv.z * w2.y + xv.w * w3.y;
        acc.z += xv.x * w0.z + xv.y * w1.z + xv.z * w2.z + xv.w * w3.z;
        acc.w += xv.x * w0.w + xv.y * w1.w + xv.z * w2.w + xv.w * w3.w;
    }
    uint2 p;
    p.x = pack_h2(acc.x, acc.y);
    p.y = pack_h2(acc.z, acc.w);
    ((uint2*)g_h)[(row0 + ri) * 16 + fi] = p;
}

// ---------------------------------------------------------------------------
// scan1: block-local exclusive prefix of padded lengths ((len+3)&~3).
// ---------------------------------------------------------------------------
__global__ __launch_bounds__(256) void scan1() {
    __shared__ int wsum[8];
    const int t = threadIdx.x;
    const int lane = t & 31;
    const int wid = t >> 5;
    const int idx = blockIdx.x * 256 + t;
    const int v  = (idx < ROWS_T) ? g_hist[idx] : 0;
    const int pv = (v + 3) & ~3;

    int x = pv;
    #pragma unroll
    for (int off = 1; off < 32; off <<= 1) {
        const int n = __shfl_up_sync(0xffffffffu, x, off);
        if (lane >= off) x += n;
    }
    if (lane == 31) wsum[wid] = x;
    __syncthreads();
    if (t < 8) {
        const int orig = wsum[t];
        int s = orig;
        #pragma unroll
        for (int off = 1; off < 8; off <<= 1) {
            const int n = __shfl_up_sync(0x000000ffu, s, off);
            if (t >= off) s += n;
        }
        wsum[t] = s - orig;
    }
    __syncthreads();
    const int ex = x - pv + wsum[wid];
    if (idx < ROWS_T) {
        g_start[idx]  = ex;
        g_cursor[idx] = ex;
    }
    if (t == 255) g_part[blockIdx.x] = ex + pv;
}

// ---------------------------------------------------------------------------
// scan2: 640 threads (20 warps) exclusive-scan the 586 block totals.
// ---------------------------------------------------------------------------
__global__ __launch_bounds__(640) void scan2() {
    __shared__ int wsum[20];
    const int t = threadIdx.x;
    const int lane = t & 31;
    const int wid = t >> 5;
    const int v = (t < NB1) ? g_part[t] : 0;

    int x = v;
    #pragma unroll
    for (int off = 1; off < 32; off <<= 1) {
        const int n = __shfl_up_sync(0xffffffffu, x, off);
        if (lane >= off) x += n;
    }
    if (lane == 31) wsum[wid] = x;
    __syncthreads();
    if (t < 32) {
        const int orig = (t < 20) ? wsum[t] : 0;
        int s = orig;
        #pragma unroll
        for (int off = 1; off < 32; off <<= 1) {
            const int n = __shfl_up_sync(0xffffffffu, s, off);
            if (t >= off) s += n;
        }
        if (t < 20) wsum[t] = s - orig;
    }
    __syncthreads();
    if (t < NB1) g_part[t] = x - v + wsum[wid];
}

// ---------------------------------------------------------------------------
// Scatter: 4 edges per thread; all four cursor atomics issued before any
// dependent store (4 independent chains for MLP); one 4 B store per edge.
// ---------------------------------------------------------------------------
__global__ __launch_bounds__(256) void scatter(const float* __restrict__ vals,
                                               const int*   __restrict__ rows,
                                               const int*   __restrict__ cols) {
    const int p = blockIdx.x * 256 + threadIdx.x;
    if (p >= EDGES_T / 4) return;
    const int4   rp = ((const int4*)(rows + NNZ))[p];
    const int4   cp = ((const int4*)(cols + NNZ))[p];
    const float4 vp = ((const float4*)(vals + NNZ))[p];
    const int base = ((4 * p) / NNZ) * NNODES;   // quad never crosses a block

    const int bk0 = base + rp.x;
    const int bk1 = base + rp.y;
    const int bk2 = base + rp.z;
    const int bk3 = base + rp.w;
    const int l0 = atomicAdd(&g_cursor[bk0], 1);
    const int l1 = atomicAdd(&g_cursor[bk1], 1);
    const int l2 = atomicAdd(&g_cursor[bk2], 1);
    const int l3 = atomicAdd(&g_cursor[bk3], 1);
    g_ep[l0 + g_part[bk0 >> 8]] = pack_edge(cp.x, vp.x);
    g_ep[l1 + g_part[bk1 >> 8]] = pack_edge(cp.y, vp.y);
    g_ep[l2 + g_part[bk2 >> 8]] = pack_edge(cp.z, vp.z);
    g_ep[l3 + g_part[bk3 >> 8]] = pack_edge(cp.w, vp.w);
}

// ---------------------------------------------------------------------------
// SpMM-1 (CSR gather, 8-edge batched): y[b][r] = filt * sum v_e * h[c_e]
// ---------------------------------------------------------------------------
__global__ __launch_bounds__(256) void spmm1_csr(const float* __restrict__ filt) {
    const int gid = blockIdx.x * 256 + threadIdx.x;
    const int row = gid >> 3;
    if (row >= ROWS_T) return;
    const int q = gid & 7;
    const int beg = g_start[row] + g_part[row >> 8];
    const int len = g_hist[row];
    const int b = row / NNODES;
    const int r = row - b * NNODES;

    float acc[8];
    #pragma unroll
    for (int k = 0; k < 8; k++) acc[k] = 0.f;

    const unsigned* ep = g_ep + beg;
    int j = 0;
    for (; j + 8 <= len; j += 8) {
        const uint4 ea = *(const uint4*)(ep + j);
        const uint4 eb = *(const uint4*)(ep + j + 4);
        const uint4 h0 = g_h[(size_t)(ea.x & 0xffffu) * 8 + q];
        const uint4 h1 = g_h[(size_t)(ea.y & 0xffffu) * 8 + q];
        const uint4 h2 = g_h[(size_t)(ea.z & 0xffffu) * 8 + q];
        const uint4 h3 = g_h[(size_t)(ea.w & 0xffffu) * 8 + q];
        const uint4 h4 = g_h[(size_t)(eb.x & 0xffffu) * 8 + q];
        const uint4 h5 = g_h[(size_t)(eb.y & 0xffffu) * 8 + q];
        const uint4 h6 = g_h[(size_t)(eb.z & 0xffffu) * 8 + q];
        const uint4 h7 = g_h[(size_t)(eb.w & 0xffffu) * 8 + q];
        accum8(acc, edge_val(ea.x), h0);
        accum8(acc, edge_val(ea.y), h1);
        accum8(acc, edge_val(ea.z), h2);
        accum8(acc, edge_val(ea.w), h3);
        accum8(acc, edge_val(eb.x), h4);
        accum8(acc, edge_val(eb.y), h5);
        accum8(acc, edge_val(eb.z), h6);
        accum8(acc, edge_val(eb.w), h7);
    }
    for (; j + 4 <= len; j += 4) {
        const uint4 ea = *(const uint4*)(ep + j);
        const uint4 h0 = g_h[(size_t)(ea.x & 0xffffu) * 8 + q];
        const uint4 h1 = g_h[(size_t)(ea.y & 0xffffu) * 8 + q];
        const uint4 h2 = g_h[(size_t)(ea.z & 0xffffu) * 8 + q];
        const uint4 h3 = g_h[(size_t)(ea.w & 0xffffu) * 8 + q];
        accum8(acc, edge_val(ea.x), h0);
        accum8(acc, edge_val(ea.y), h1);
        accum8(acc, edge_val(ea.z), h2);
        accum8(acc, edge_val(ea.w), h3);
    }
    for (; j < len; j++) {
        const unsigned e = ep[j];
        const uint4 h = g_h[(size_t)(e & 0xffffu) * 8 + q];
        accum8(acc, edge_val(e), h);
    }

    const float f = filt[(size_t)(b + 1) * NNODES + r];
    uint4 o;
    o.x = pack_h2(f * acc[0], f * acc[1]);
    o.y = pack_h2(f * acc[2], f * acc[3]);
    o.z = pack_h2(f * acc[4], f * acc[5]);
    o.w = pack_h2(f * acc[6], f * acc[7]);
    g_y[(size_t)row * 8 + q] = o;
}

// ---------------------------------------------------------------------------
// SpMM-2 (CSR gather, 8-edge batched): out[r] = bias + sum_b sum v_e * y[b][c]
// Restores g_hist = 0 after the final read (warp-local slot; warp-wide LDG
// precedes lane-0's STG in program order; no other warp reads the slot).
// ---------------------------------------------------------------------------
__global__ __launch_bounds__(256) void spmm2_csr(float* __restrict__ out,
                                                 const float* __restrict__ bias) {
    const int gid = blockIdx.x * 256 + threadIdx.x;
    const int r = gid >> 3;
    if (r >= NNODES) return;
    const int q = gid & 7;

    float acc[8];
    {
        const float4 b0 = ((const float4*)bias)[q * 2 + 0];
        const float4 b1 = ((const float4*)bias)[q * 2 + 1];
        acc[0] = b0.x; acc[1] = b0.y; acc[2] = b0.z; acc[3] = b0.w;
        acc[4] = b1.x; acc[5] = b1.y; acc[6] = b1.z; acc[7] = b1.w;
    }

    #pragma unroll
    for (int b = 0; b < ACT_B; b++) {
        const int row = b * NNODES + r;
        const int beg = g_start[row] + g_part[row >> 8];
        const int len = g_hist[row];
        if (q == 0) g_hist[row] = 0;
        const size_t ybase = (size_t)b * NNODES * 8;
        const unsigned* ep = g_ep + beg;
        int j = 0;
        for (; j + 8 <= len; j += 8) {
            const uint4 ea = *(const uint4*)(ep + j);
            const uint4 eb = *(const uint4*)(ep + j + 4);
            const uint4 y0 = g_y[ybase + (size_t)(ea.x & 0xffffu) * 8 + q];
            const uint4 y1 = g_y[ybase + (size_t)(ea.y & 0xffffu) * 8 + q];
            const uint4 y2 = g_y[ybase + (size_t)(ea.z & 0xffffu) * 8 + q];
            const uint4 y3 = g_y[ybase + (size_t)(ea.w & 0xffffu) * 8 + q];
            const uint4 y4 = g_y[ybase + (size_t)(eb.x & 0xffffu) * 8 + q];
            const uint4 y5 = g_y[ybase + (size_t)(eb.y & 0xffffu) * 8 + q];
            const uint4 y6 = g_y[ybase + (size_t)(eb.z & 0xffffu) * 8 + q];
            const uint4 y7 = g_y[ybase + (size_t)(eb.w & 0xffffu) * 8 + q];
            accum8(acc, edge_val(ea.x), y0);
            accum8(acc, edge_val(ea.y), y1);
            accum8(acc, edge_val(ea.z), y2);
            accum8(acc, edge_val(ea.w), y3);
            accum8(acc, edge_val(eb.x), y4);
            accum8(acc, edge_val(eb.y), y5);
            accum8(acc, edge_val(eb.z), y6);
            accum8(acc, edge_val(eb.w), y7);
        }
        for (; j + 4 <= len; j += 4) {
            const uint4 ea = *(const uint4*)(ep + j);
            const uint4 y0 = g_y[ybase + (size_t)(ea.x & 0xffffu) * 8 + q];
            const uint4 y1 = g_y[ybase + (size_t)(ea.y & 0xffffu) * 8 + q];
            const uint4 y2 = g_y[ybase + (size_t)(ea.z & 0xffffu) * 8 + q];
            const uint4 y3 = g_y[ybase + (size_t)(ea.w & 0xffffu) * 8 + q];
            accum8(acc, edge_val(ea.x), y0);
            accum8(acc, edge_val(ea.y), y1);
            accum8(acc, edge_val(ea.z), y2);
            accum8(acc, edge_val(ea.w), y3);
        }
        for (; j < len; j++) {
            const unsigned e = ep[j];
            const uint4 yv = g_y[ybase + (size_t)(e & 0xffffu) * 8 + q];
            accum8(acc, edge_val(e), yv);
        }
    }
    float4* op = (float4*)(out + (size_t)r * F_OUT + q * 8);
    op[0] = make_float4(acc[0], acc[1], acc[2], acc[3]);
    op[1] = make_float4(acc[4], acc[5], acc[6], acc[7]);
}

// ---------------------------------------------------------------------------
// Launch order: gemm(+hist), scan1, scan2, scatter, spmm1, spmm2(+restore)
// ---------------------------------------------------------------------------
extern "C" void kernel_launch(void* const* d_in, const int* in_sizes, int n_in,
                              void* d_out, int out_size) {
    const float* x    = (const float*)d_in[0];
    const float* wgt  = (const float*)d_in[1];
    const float* filt = (const float*)d_in[2];
    const float* bias = (const float*)d_in[3];
    const float* vals = (const float*)d_in[4];
    const int*   rows = (const int*)d_in[5];
    const int*   cols = (const int*)d_in[6];
    float* out = (float*)d_out;

    gemm_xw<<<NNODES / 16, 256>>>(x, wgt, rows);                   // #1
    scan1<<<NB1, 256>>>();                                         // #2
    scan2<<<1, 640>>>();                                           // #3
    scatter<<<(EDGES_T / 4 + 255) / 256, 256>>>(vals, rows, cols); // #4
    spmm1_csr<<<(ROWS_T * 8 + 255) / 256, 256>>>(filt);            // #5
    spmm2_csr<<<(NNODES * 8 + 255) / 256, 256>>>(out, bias);       // #6
}

// round 13
// speedup vs baseline: 1.0076x; 1.0076x over previous
#include <cuda_runtime.h>
#include <cuda_fp16.h>
#include <cstdint>

// Problem constants (fixed by the dataset)
#define NNODES 50000
#define LEV 2
#define RR 2
#define BLK (RR*LEV)          // 4 framelet blocks
#define NNZ 800000
#define F_IN 128
#define F_OUT 64
#define ACT_B (BLK - (LEV-1)) // 3 active blocks (block 0's y is never used)
#define ROWS_T (ACT_B * NNODES)   // 150000 (b, r) rows
#define EDGES_T (ACT_B * NNZ)     // 2400000 active edges
#define NB1 ((ROWS_T + 255) / 256)  // 586 level-1 scan blocks
#define GEMM_THREADS 800000         // 3125 blocks * 256
#define PADDED_E (EDGES_T + 3 * ROWS_T)   // 2,850,000 (pad-4 worst case)

// ---------------------------------------------------------------------------
// Scratch. h, y are fp16 (half2-packed): one row = 64 halves = 128 B = 8
// uint4. Edge list is PACKED AoS: edge = 4 B (uint16 col | fp16 val << 16);
// row segments padded to %4 so uint4 loads of 4 edges stay 16B-aligned.
//
// g_rank[e] = this edge's rank within its (b,r) row, captured from the
// histogram atomicAdd return — scatter then needs NO atomics at all.
//
// Cross-replay invariant: g_hist == 0 at entry. BSS zero-init covers the
// first run; spmm2_csr restores zero after its final read on every replay.
// ---------------------------------------------------------------------------
__device__ uint4  g_h[(size_t)NNODES * 8];     // 6.4 MB
__device__ uint4  g_y[(size_t)ROWS_T * 8];     // 19.2 MB
__device__ int    g_hist[ROWS_T];              // per-(b,r) nnz
__device__ int    g_start[ROWS_T];             // block-local padded excl prefix
__device__ int    g_part[1024];                // scan block partials
__device__ int    g_rank[EDGES_T];             // 9.6 MB, edge rank within row
__device__ uint4  g_ep4[(PADDED_E + 3) / 4];   // packed edges, 11.4 MB
#define g_ep ((unsigned*)g_ep4)

__device__ __forceinline__ unsigned pack_h2(float a, float b) {
    __half2 h = __floats2half2_rn(a, b);
    return *reinterpret_cast<unsigned*>(&h);
}
__device__ __forceinline__ float2 unpack_h2(unsigned u) {
    __half2 h = *reinterpret_cast<__half2*>(&u);
    return __half22float2(h);
}
__device__ __forceinline__ unsigned pack_edge(int c, float v) {
    return (unsigned)c | ((unsigned)__half_as_ushort(__float2half_rn(v)) << 16);
}
__device__ __forceinline__ float edge_val(unsigned e) {
    return __half2float(__ushort_as_half((unsigned short)(e >> 16)));
}
__device__ __forceinline__ void accum8(float* acc, float v, uint4 hv) {
    const float2 f0 = unpack_h2(hv.x);
    const float2 f1 = unpack_h2(hv.y);
    const float2 f2 = unpack_h2(hv.z);
    const float2 f3 = unpack_h2(hv.w);
    acc[0] += v * f0.x; acc[1] += v * f0.y;
    acc[2] += v * f1.x; acc[3] += v * f1.y;
    acc[4] += v * f2.x; acc[5] += v * f2.y;
    acc[6] += v * f3.x; acc[7] += v * f3.y;
}

// ---------------------------------------------------------------------------
// h = x @ W (fp32 compute, fp16 store) + fused histogram WITH rank capture.
// ---------------------------------------------------------------------------
__global__ __launch_bounds__(256) void gemm_xw(const float* __restrict__ x,
                                               const float* __restrict__ w,
                                               const int*   __restrict__ rows) {
    const int t  = threadIdx.x;
    const int gt = blockIdx.x * 256 + t;

    __shared__ float4 ws[F_IN * (F_OUT/4)];   // 32 KB
    __shared__ float4 xs[16 * (F_IN/4)];      // 8 KB

    // 3 strided edges per thread (3 * 800000 == EDGES_T).
    // The atomic return IS the edge's rank within its row; store it
    // (coalesced). Latency hides under the GEMM below.
    #pragma unroll
    for (int s = 0; s < 3; s++) {
        const int e = gt + s * GEMM_THREADS;
        const int b = e / NNZ;
        const int i = e - b * NNZ;
        const int r = rows[(size_t)(b + 1) * NNZ + i];
        g_rank[e] = atomicAdd(&g_hist[b * NNODES + r], 1);
    }

    #pragma unroll
    for (int i = 0; i < 8; i++)
        ws[t + i * 256] = ((const float4*)w)[t + i * 256];

    const size_t row0 = (size_t)blockIdx.x * 16;
    #pragma unroll
    for (int i = 0; i < 2; i++)
        xs[t + i * 256] = ((const float4*)x)[row0 * (F_IN/4) + t + i * 256];

    __syncthreads();

    const int fi = t & 15;
    const int ri = t >> 4;
    float4 acc = make_float4(0.f, 0.f, 0.f, 0.f);

    #pragma unroll
    for (int k = 0; k < F_IN; k += 4) {
        const float4 xv = xs[ri * (F_IN/4) + (k >> 2)];
        const float4 w0 = ws[(k + 0) * 16 + fi];
        const float4 w1 = ws[(k + 1) * 16 + fi];
        const float4 w2 = ws[(k + 2) * 16 + fi];
        const float4 w3 = ws[(k + 3) * 16 + fi];
        acc.x += xv.x * w0.x + xv.y * w1.x + xv.z * w2.x + xv.w * w3.x;
        acc.y += xv.x * w0.y + xv.y * w1.y + xv.z * w2.y + xv.w * w3.y;
        acc.z += xv.x * w0.z + xv.y * w1.z + xv.z * w2.z + xv.w * w3.z;
        acc.w += xv.x * w0.w + xv.y * w1.w + xv.z * w2.w + xv.w * w3.w;
    }
    uint2 p;
    p.x = pack_h2(acc.x, acc.y);
    p.y = pack_h2(acc.z, acc.w);
    ((uint2*)g_h)[(row0 + ri) * 16 + fi] = p;
}

// ---------------------------------------------------------------------------
// scan1: block-local exclusive prefix of padded lengths ((len+3)&~3).
// ---------------------------------------------------------------------------
__global__ __launch_bounds__(256) void scan1() {
    __shared__ int wsum[8];
    const int t = threadIdx.x;
    const int lane = t & 31;
    const int wid = t >> 5;
    const int idx = blockIdx.x * 256 + t;
    const int v  = (idx < ROWS_T) ? g_hist[idx] : 0;
    const int pv = (v + 3) & ~3;

    int x = pv;
    #pragma unroll
    for (int off = 1; off < 32; off <<= 1) {
        const int n = __shfl_up_sync(0xffffffffu, x, off);
        if (lane >= off) x += n;
    }
    if (lane == 31) wsum[wid] = x;
    __syncthreads();
    if (t < 8) {
        const int orig = wsum[t];
        int s = orig;
        #pragma unroll
        for (int off = 1; off < 8; off <<= 1) {
            const int n = __shfl_up_sync(0x000000ffu, s, off);
            if (t >= off) s += n;
        }
        wsum[t] = s - orig;
    }
    __syncthreads();
    const int ex = x - pv + wsum[wid];
    if (idx < ROWS_T) g_start[idx] = ex;
    if (t == 255) g_part[blockIdx.x] = ex + pv;
}

// ---------------------------------------------------------------------------
// scan2: 640 threads (20 warps) exclusive-scan the 586 block totals.
// ---------------------------------------------------------------------------
__global__ __launch_bounds__(640) void scan2() {
    __shared__ int wsum[20];
    const int t = threadIdx.x;
    const int lane = t & 31;
    const int wid = t >> 5;
    const int v = (t < NB1) ? g_part[t] : 0;

    int x = v;
    #pragma unroll
    for (int off = 1; off < 32; off <<= 1) {
        const int n = __shfl_up_sync(0xffffffffu, x, off);
        if (lane >= off) x += n;
    }
    if (lane == 31) wsum[wid] = x;
    __syncthreads();
    if (t < 32) {
        const int orig = (t < 20) ? wsum[t] : 0;
        int s = orig;
        #pragma unroll
        for (int off = 1; off < 32; off <<= 1) {
            const int n = __shfl_up_sync(0xffffffffu, s, off);
            if (t >= off) s += n;
        }
        if (t < 20) wsum[t] = s - orig;
    }
    __syncthreads();
    if (t < NB1) g_part[t] = x - v + wsum[wid];
}

// ---------------------------------------------------------------------------
// Scatter: ATOMIC-FREE. pos = g_start[bk] + g_part[bk>>8] + rank[e].
// 4 edges per thread; all input reads coalesced/vectorized; one random 4 B
// store per edge is the only scattered traffic left.
// ---------------------------------------------------------------------------
__global__ __launch_bounds__(256) void scatter(const float* __restrict__ vals,
                                               const int*   __restrict__ rows,
                                               const int*   __restrict__ cols) {
    const int p = blockIdx.x * 256 + threadIdx.x;
    if (p >= EDGES_T / 4) return;
    const int4   rp = ((const int4*)(rows + NNZ))[p];
    const int4   cp = ((const int4*)(cols + NNZ))[p];
    const float4 vp = ((const float4*)(vals + NNZ))[p];
    const int4   kp = ((const int4*)g_rank)[p];
    const int base = ((4 * p) / NNZ) * NNODES;   // quad never crosses a block

    const int bk0 = base + rp.x;
    const int bk1 = base + rp.y;
    const int bk2 = base + rp.z;
    const int bk3 = base + rp.w;
    g_ep[g_start[bk0] + g_part[bk0 >> 8] + kp.x] = pack_edge(cp.x, vp.x);
    g_ep[g_start[bk1] + g_part[bk1 >> 8] + kp.y] = pack_edge(cp.y, vp.y);
    g_ep[g_start[bk2] + g_part[bk2 >> 8] + kp.z] = pack_edge(cp.z, vp.z);
    g_ep[g_start[bk3] + g_part[bk3 >> 8] + kp.w] = pack_edge(cp.w, vp.w);
}

// ---------------------------------------------------------------------------
// SpMM-1 (CSR gather, 8-edge batched): y[b][r] = filt * sum v_e * h[c_e]
// ---------------------------------------------------------------------------
__global__ __launch_bounds__(256) void spmm1_csr(const float* __restrict__ filt) {
    const int gid = blockIdx.x * 256 + threadIdx.x;
    const int row = gid >> 3;
    if (row >= ROWS_T) return;
    const int q = gid & 7;
    const int beg = g_start[row] + g_part[row >> 8];
    const int len = g_hist[row];
    const int b = row / NNODES;
    const int r = row - b * NNODES;

    float acc[8];
    #pragma unroll
    for (int k = 0; k < 8; k++) acc[k] = 0.f;

    const unsigned* ep = g_ep + beg;
    int j = 0;
    for (; j + 8 <= len; j += 8) {
        const uint4 ea = *(const uint4*)(ep + j);
        const uint4 eb = *(const uint4*)(ep + j + 4);
        const uint4 h0 = g_h[(size_t)(ea.x & 0xffffu) * 8 + q];
        const uint4 h1 = g_h[(size_t)(ea.y & 0xffffu) * 8 + q];
        const uint4 h2 = g_h[(size_t)(ea.z & 0xffffu) * 8 + q];
        const uint4 h3 = g_h[(size_t)(ea.w & 0xffffu) * 8 + q];
        const uint4 h4 = g_h[(size_t)(eb.x & 0xffffu) * 8 + q];
        const uint4 h5 = g_h[(size_t)(eb.y & 0xffffu) * 8 + q];
        const uint4 h6 = g_h[(size_t)(eb.z & 0xffffu) * 8 + q];
        const uint4 h7 = g_h[(size_t)(eb.w & 0xffffu) * 8 + q];
        accum8(acc, edge_val(ea.x), h0);
        accum8(acc, edge_val(ea.y), h1);
        accum8(acc, edge_val(ea.z), h2);
        accum8(acc, edge_val(ea.w), h3);
        accum8(acc, edge_val(eb.x), h4);
        accum8(acc, edge_val(eb.y), h5);
        accum8(acc, edge_val(eb.z), h6);
        accum8(acc, edge_val(eb.w), h7);
    }
    for (; j + 4 <= len; j += 4) {
        const uint4 ea = *(const uint4*)(ep + j);
        const uint4 h0 = g_h[(size_t)(ea.x & 0xffffu) * 8 + q];
        const uint4 h1 = g_h[(size_t)(ea.y & 0xffffu) * 8 + q];
        const uint4 h2 = g_h[(size_t)(ea.z & 0xffffu) * 8 + q];
        const uint4 h3 = g_h[(size_t)(ea.w & 0xffffu) * 8 + q];
        accum8(acc, edge_val(ea.x), h0);
        accum8(acc, edge_val(ea.y), h1);
        accum8(acc, edge_val(ea.z), h2);
        accum8(acc, edge_val(ea.w), h3);
    }
    for (; j < len; j++) {
        const unsigned e = ep[j];
        const uint4 h = g_h[(size_t)(e & 0xffffu) * 8 + q];
        accum8(acc, edge_val(e), h);
    }

    const float f = filt[(size_t)(b + 1) * NNODES + r];
    uint4 o;
    o.x = pack_h2(f * acc[0], f * acc[1]);
    o.y = pack_h2(f * acc[2], f * acc[3]);
    o.z = pack_h2(f * acc[4], f * acc[5]);
    o.w = pack_h2(f * acc[6], f * acc[7]);
    g_y[(size_t)row * 8 + q] = o;
}

// ---------------------------------------------------------------------------
// SpMM-2 (CSR gather, 8-edge batched): out[r] = bias + sum_b sum v_e * y[b][c]
// Restores g_hist = 0 after the final read (warp-local slot; warp-wide LDG
// precedes lane-0's STG in program order; no other warp reads the slot).
// ---------------------------------------------------------------------------
__global__ __launch_bounds__(256) void spmm2_csr(float* __restrict__ out,
                                                 const float* __restrict__ bias) {
    const int gid = blockIdx.x * 256 + threadIdx.x;
    const int r = gid >> 3;
    if (r >= NNODES) return;
    const int q = gid & 7;

    float acc[8];
    {
        const float4 b0 = ((const float4*)bias)[q * 2 + 0];
        const float4 b1 = ((const float4*)bias)[q * 2 + 1];
        acc[0] = b0.x; acc[1] = b0.y; acc[2] = b0.z; acc[3] = b0.w;
        acc[4] = b1.x; acc[5] = b1.y; acc[6] = b1.z; acc[7] = b1.w;
    }

    #pragma unroll
    for (int b = 0; b < ACT_B; b++) {
        const int row = b * NNODES + r;
        const int beg = g_start[row] + g_part[row >> 8];
        const int len = g_hist[row];
        if (q == 0) g_hist[row] = 0;
        const size_t ybase = (size_t)b * NNODES * 8;
        const unsigned* ep = g_ep + beg;
        int j = 0;
        for (; j + 8 <= len; j += 8) {
            const uint4 ea = *(const uint4*)(ep + j);
            const uint4 eb = *(const uint4*)(ep + j + 4);
            const uint4 y0 = g_y[ybase + (size_t)(ea.x & 0xffffu) * 8 + q];
            const uint4 y1 = g_y[ybase + (size_t)(ea.y & 0xffffu) * 8 + q];
            const uint4 y2 = g_y[ybase + (size_t)(ea.z & 0xffffu) * 8 + q];
            const uint4 y3 = g_y[ybase + (size_t)(ea.w & 0xffffu) * 8 + q];
            const uint4 y4 = g_y[ybase + (size_t)(eb.x & 0xffffu) * 8 + q];
            const uint4 y5 = g_y[ybase + (size_t)(eb.y & 0xffffu) * 8 + q];
            const uint4 y6 = g_y[ybase + (size_t)(eb.z & 0xffffu) * 8 + q];
            const uint4 y7 = g_y[ybase + (size_t)(eb.w & 0xffffu) * 8 + q];
            accum8(acc, edge_val(ea.x), y0);
            accum8(acc, edge_val(ea.y), y1);
            accum8(acc, edge_val(ea.z), y2);
            accum8(acc, edge_val(ea.w), y3);
            accum8(acc, edge_val(eb.x), y4);
            accum8(acc, edge_val(eb.y), y5);
            accum8(acc, edge_val(eb.z), y6);
            accum8(acc, edge_val(eb.w), y7);
        }
        for (; j + 4 <= len; j += 4) {
            const uint4 ea = *(const uint4*)(ep + j);
            const uint4 y0 = g_y[ybase + (size_t)(ea.x & 0xffffu) * 8 + q];
            const uint4 y1 = g_y[ybase + (size_t)(ea.y & 0xffffu) * 8 + q];
            const uint4 y2 = g_y[ybase + (size_t)(ea.z & 0xffffu) * 8 + q];
            const uint4 y3 = g_y[ybase + (size_t)(ea.w & 0xffffu) * 8 + q];
            accum8(acc, edge_val(ea.x), y0);
            accum8(acc, edge_val(ea.y), y1);
            accum8(acc, edge_val(ea.z), y2);
            accum8(acc, edge_val(ea.w), y3);
        }
        for (; j < len; j++) {
            const unsigned e = ep[j];
            const uint4 yv = g_y[ybase + (size_t)(e & 0xffffu) * 8 + q];
            accum8(acc, edge_val(e), yv);
        }
    }
    float4* op = (float4*)(out + (size_t)r * F_OUT + q * 8);
    op[0] = make_float4(acc[0], acc[1], acc[2], acc[3]);
    op[1] = make_float4(acc[4], acc[5], acc[6], acc[7]);
}

// ---------------------------------------------------------------------------
// Launch: gemm(+hist+rank), scan1, scan2, scatter(no atomics), spmm1, spmm2
// ---------------------------------------------------------------------------
extern "C" void kernel_launch(void* const* d_in, const int* in_sizes, int n_in,
                              void* d_out, int out_size) {
    const float* x    = (const float*)d_in[0];
    const float* wgt  = (const float*)d_in[1];
    const float* filt = (const float*)d_in[2];
    const float* bias = (const float*)d_in[3];
    const float* vals = (const float*)d_in[4];
    const int*   rows = (const int*)d_in[5];
    const int*   cols = (const int*)d_in[6];
    float* out = (float*)d_out;

    gemm_xw<<<NNODES / 16, 256>>>(x, wgt, rows);                   // #1
    scan1<<<NB1, 256>>>();                                         // #2
    scan2<<<1, 640>>>();                                           // #3
    scatter<<<(EDGES_T / 4 + 255) / 256, 256>>>(vals, rows, cols); // #4
    spmm1_csr<<<(ROWS_T * 8 + 255) / 256, 256>>>(filt);            // #5
    spmm2_csr<<<(NNODES * 8 + 255) / 256, 256>>>(out, bias);       // #6
}